// round 10
// baseline (speedup 1.0000x reference)
#include <cuda_runtime.h>
#include <cstdint>

// AnchorMatcher: N anchors x M gt boxes -> packed float32 out[6N]:
//   [0,N): cls targets, [N,5N): reg targets (float4), [5N,6N): pos mask 0/1.
// Single fused kernel: IoU pass + epilogue + last-block forced-positive patch.

#define MAXN   262144   // >= 200000
#define MAXM   128
#define POS_THR 0.5f
#define NEG_THR 0.4f
#define TPB     256      // threads per block; 1 anchor per thread

// Scratch (no allocations allowed -> __device__ globals; zero-init at load)
__device__ int                g_midx[MAXN];
__device__ unsigned long long g_packed[MAXM];  // per-gt (iou_bits<<32)|(~anchor_idx)
__device__ unsigned int       g_ticket;        // last-block-done counter

__global__ __launch_bounds__(TPB) void k_iou(
    const float4* __restrict__ anchors,
    const float4* __restrict__ gts,
    const int*    __restrict__ labels,
    float*        __restrict__ out,
    int N, int M)
{
    __shared__ float4             sg[MAXM];   // gt boxes
    __shared__ float              sga[MAXM];  // gt areas
    __shared__ int                slab[MAXM]; // gt labels
    __shared__ unsigned long long sp[MAXM];   // per-gt packed best (block)
    __shared__ bool               s_last;     // last-block flag

    const int tid = threadIdx.x;
    if (tid < M) {
        float4 g = gts[tid];
        sg[tid]   = g;
        sga[tid]  = (g.z - g.x) * (g.w - g.y);
        slab[tid] = labels[tid];
        sp[tid]   = 0ULL;
    }
    __syncthreads();

    const int  i     = blockIdx.x * TPB + tid;     // one anchor per thread
    const bool valid = (i < N);

    // Invalid threads get a degenerate box at the origin: intersection width/
    // height clamp to 0 against ANY gt (boxes have positive extent), so
    // iou == +0 exactly -> bits==0 -> the nonzero gate below never fires.
    const float4 a = valid ? anchors[i] : make_float4(0.f, 0.f, 0.f, 0.f);
    const float areaA = (a.z - a.x) * (a.w - a.y);
    const unsigned inv = 0xFFFFFFFFu - (unsigned)i;  // key low word (min-index wins)

    // shared address of sp[] for inline-PTX RED
    const unsigned sp_base = (unsigned)__cvta_generic_to_shared(sp);

    float best = -1.0f;
    int   bj   = 0;

    // ---------------- hot loop: no branches, no BSSY ----------------
    #pragma unroll 4
    for (int j = 0; j < M; ++j) {
        const float4 g  = sg[j];
        const float  ga = sga[j];

        const float w = fmaxf(fminf(a.z, g.z) - fmaxf(a.x, g.x), 0.0f);
        const float h = fmaxf(fminf(a.w, g.w) - fmaxf(a.y, g.y), 0.0f);
        const float inter = w * h;
        // IEEE RN division: XLA emits div.rn.f32; every threshold/argmax
        // decision must match its rounded quotient bitwise. (inter==0 cases
        // give exactly +0 with no rounding -> skipping their RED is safe.)
        const float iou = __fdiv_rn(inter, (areaA + ga) - inter);

        if (iou > best) { best = iou; bj = j; }   // strict > = first-index argmax

        const unsigned bits = __float_as_uint(iou);   // iou>=0 -> monotone in uint

        // Gate on the slot's own high word (monotone under RED.max; a stale
        // low read only admits extra REDs, never misses one). '>=' keeps the
        // min-index tie-break for equal rounded IoUs; 'bits!=0' skips the ~85%
        // of pairs with zero overlap (all-zero columns resolve to anchor 0
        // via the v==0 fallback below, matching argmax of a constant column).
        const unsigned cur = reinterpret_cast<const unsigned*>(&sp[j])[1];
        const unsigned long long key = ((unsigned long long)bits << 32) | inv;
        asm volatile(
            "{\n\t"
            ".reg .pred p, q;\n\t"
            "setp.ge.u32 p, %0, %1;\n\t"
            "setp.ne.u32 q, %0, 0;\n\t"
            "and.pred   p, p, q;\n\t"
            "@p red.shared.max.u64 [%2], %3;\n\t"
            "}"
            :: "r"(bits), "r"(cur), "r"(sp_base + (unsigned)j * 8u), "l"(key)
            : "memory");
    }

    // ---------------- epilogue: direct output writes ----------------
    if (valid) {
        g_midx[i] = bj;

        const bool pos = (best >= POS_THR);
        out[i] = pos ? (float)slab[bj] : (best < NEG_THR ? 0.0f : -1.0f);

        float4 r = make_float4(0.0f, 0.0f, 0.0f, 0.0f);
        if (pos) {
            const float eps = 1.1920929e-7f;  // FLT_EPSILON (jnp.finfo eps)
            const float4 g = sg[bj];
            const float aw = fmaxf(a.z - a.x, eps);
            const float ah = fmaxf(a.w - a.y, eps);
            r.x = __fdiv_rn((g.x + g.z) * 0.5f - (a.x + a.z) * 0.5f, aw);
            r.y = __fdiv_rn((g.y + g.w) * 0.5f - (a.y + a.w) * 0.5f, ah);
            r.z = logf(__fdiv_rn(g.z - g.x, aw));
            r.w = logf(__fdiv_rn(g.w - g.y, ah));
            // WEIGHTS = (1,1,1,1) -> identity multiply skipped.
        }
        reinterpret_cast<float4*>(out + N)[i] = r;  // out+N 16B-aligned (N%4==0)
        out[5 * N + i] = pos ? 1.0f : 0.0f;
    }

    // ---------------- flush per-gt partials, elect last block ----------------
    __syncthreads();
    if (tid < M) {
        const unsigned long long v = sp[tid];
        if (v) atomicMax(&g_packed[tid], v);
    }
    __threadfence();                 // publish outputs + g_midx + g_packed
    __syncthreads();
    if (tid == 0)
        s_last = (atomicAdd(&g_ticket, 1u) == (unsigned)(gridDim.x - 1));
    __syncthreads();

    // ---------------- last block: patch forced positives ----------------
    if (s_last) {
        __threadfence();             // acquire: see all blocks' writes
        if (tid == 0) g_ticket = 0;  // reset for next graph replay
        if (tid < M) {
            const unsigned long long v = g_packed[tid];
            g_packed[tid] = 0ULL;    // consume-and-reset for next replay

            // v==0 <=> all-zero IoU column: reference argmax picks anchor 0.
            const unsigned ai = v ? (0xFFFFFFFFu - (unsigned)(v & 0xFFFFFFFFull)) : 0u;
            if (ai < (unsigned)N) {
                const int j = g_midx[ai];
                out[ai] = (float)slab[j];

                const float eps = 1.1920929e-7f;
                const float4 av = anchors[ai];
                const float4 g  = sg[j];     // gt tile still live in this block
                const float aw = fmaxf(av.z - av.x, eps);
                const float ah = fmaxf(av.w - av.y, eps);
                float4 r;
                r.x = __fdiv_rn((g.x + g.z) * 0.5f - (av.x + av.z) * 0.5f, aw);
                r.y = __fdiv_rn((g.y + g.w) * 0.5f - (av.y + av.w) * 0.5f, ah);
                r.z = logf(__fdiv_rn(g.z - g.x, aw));
                r.w = logf(__fdiv_rn(g.w - g.y, ah));
                reinterpret_cast<float4*>(out + N)[ai] = r;

                out[5 * N + ai] = 1.0f;
            }
        }
    }
}

// ---------------------------------------------------------------------------
extern "C" void kernel_launch(void* const* d_in, const int* in_sizes, int n_in,
                              void* d_out, int out_size)
{
    const float4* anchors = (const float4*)d_in[0];
    const float4* gts     = (const float4*)d_in[1];
    const int*    labels  = (const int*)d_in[2];
    float*        out     = (float*)d_out;

    const int N = in_sizes[0] / 4;
    const int M = in_sizes[1] / 4;   // 128

    const int blocks = (N + TPB - 1) / TPB;

    k_iou<<<blocks, TPB>>>(anchors, gts, labels, out, N, M);
}

// round 14
// speedup vs baseline: 1.4494x; 1.4494x over previous
#include <cuda_runtime.h>
#include <cstdint>

// AnchorMatcher: N anchors x M gt boxes -> packed float32 out[6N]:
//   [0,N): cls targets, [N,5N): reg targets (float4), [5N,6N): pos mask 0/1.
// Single fused kernel. Hot loop is DIVISION-FREE: a conservative FFMA gate
// (monotone-rounding argument, zero false negatives) sends the rare
// candidate pairs to a slow path doing the exact IEEE div + bookkeeping.

#define MAXN   262144   // >= 200000
#define MAXM   128
#define POS_THR 0.5f
#define NEG_THR 0.4f
#define TPB     256
#define ADJ     0.99999619f   // 1 - 2^-18: gate slack >> all rounding error

// Scratch (no allocations allowed -> __device__ globals; zero-init at load)
__device__ int                g_midx[MAXN];
__device__ unsigned long long g_packed[MAXM];  // per-gt (iou_bits<<32)|(~anchor_idx)
__device__ unsigned int       g_ticket;        // last-block-done counter

__global__ __launch_bounds__(TPB) void k_iou(
    const float4* __restrict__ anchors,
    const float4* __restrict__ gts,
    const int*    __restrict__ labels,
    float*        __restrict__ out,
    int N, int M)
{
    __shared__ float4             sg[MAXM];     // gt boxes
    __shared__ float2             smeta[MAXM];  // {gt area, adj block-best iou}
    __shared__ int                slab[MAXM];   // gt labels
    __shared__ unsigned long long sp[MAXM];     // per-gt packed best (block)
    __shared__ bool               s_last;

    const int tid = threadIdx.x;
    if (tid < M) {
        float4 g = gts[tid];
        sg[tid]    = g;
        smeta[tid] = make_float2((g.z - g.x) * (g.w - g.y), 0.0f);
        slab[tid]  = labels[tid];
        sp[tid]    = 0ULL;
    }
    __syncthreads();

    const int  i     = blockIdx.x * TPB + tid;   // one anchor per thread
    const bool valid = (i < N);

    // Invalid threads: degenerate box -> inter == 0 vs every gt -> gate never
    // fires (denom = ga > 0, so no NaN anywhere).
    const float4 a = valid ? anchors[i] : make_float4(0.f, 0.f, 0.f, 0.f);
    const float areaA = (a.z - a.x) * (a.w - a.y);
    const unsigned inv = 0xFFFFFFFFu - (unsigned)i;  // key low word (min-index wins)

    const unsigned sp_base = (unsigned)__cvta_generic_to_shared(sp);
    const unsigned sm_base = (unsigned)__cvta_generic_to_shared(smeta);

    float best = 0.0f;   // rounded max IoU so far (argmax of all-zero col = j 0)
    float qadj = 0.0f;   // best * ADJ (per-anchor gate baseline)
    int   bj   = 0;

    #pragma unroll 4
    for (int j = 0; j < M; ++j) {
        const float4 g = sg[j];
        const float2 meta = smeta[j];            // {ga, block-adj-best}  LDS.64

        const float w = fmaxf(fminf(a.z, g.z) - fmaxf(a.x, g.x), 0.0f);
        const float h = fmaxf(fminf(a.w, g.w) - fmaxf(a.y, g.y), 0.0f);
        const float inter = w * h;
        const float denom = (areaA + meta.x) - inter;   // > 0 always

        // Division-free gate. A pair can change either argmax only if its
        // rational IoU exceeds a baseline's rounding boundary; baselines are
        // pre-scaled by ADJ so the single-rounded FFMA test has zero false
        // negatives. min() merges per-anchor and per-gt baselines (most
        // permissive). Baseline reads may be stale-low: only admits extras.
        const float mn = fminf(qadj, meta.y);
        if (fmaf(mn, denom, -inter) < 0.0f) {
            // ---- slow path: exact IEEE division ----
            // XLA emits div.rn.f32; thresholds/argmax must match its rounded
            // quotient bitwise.
            const float q = __fdiv_rn(inter, denom);

            // per-anchor argmax: strict > in ascending j = first-index
            if (q > best) { best = q; bj = j; qadj = q * ADJ; }

            // per-gt argmax: packed monotone key, predicated RED (no BSSY)
            const unsigned bits = __float_as_uint(q);   // q > 0 here
            const unsigned cur  = reinterpret_cast<const unsigned*>(&sp[j])[1];
            const unsigned long long key = ((unsigned long long)bits << 32) | inv;
            asm volatile(
                "{\n\t"
                ".reg .pred p;\n\t"
                "setp.ge.u32 p, %0, %1;\n\t"
                "@p red.shared.max.u64 [%2], %3;\n\t"
                "}"
                :: "r"(bits), "r"(cur), "r"(sp_base + (unsigned)j * 8u), "l"(key)
                : "memory");

            // refresh block per-gt gate baseline (racy lower-overwrite = safe)
            const float qa = q * ADJ;
            if (qa > meta.y) {
                asm volatile("st.shared.f32 [%0], %1;"
                             :: "r"(sm_base + (unsigned)j * 8u + 4u), "f"(qa)
                             : "memory");
            }
        }
    }

    // ---------------- epilogue: direct output writes ----------------
    if (valid) {
        g_midx[i] = bj;

        const bool pos = (best >= POS_THR);
        out[i] = pos ? (float)slab[bj] : (best < NEG_THR ? 0.0f : -1.0f);

        float4 r = make_float4(0.0f, 0.0f, 0.0f, 0.0f);
        if (pos) {
            const float eps = 1.1920929e-7f;  // FLT_EPSILON (jnp.finfo eps)
            const float4 g = sg[bj];
            const float aw = fmaxf(a.z - a.x, eps);
            const float ah = fmaxf(a.w - a.y, eps);
            r.x = __fdiv_rn((g.x + g.z) * 0.5f - (a.x + a.z) * 0.5f, aw);
            r.y = __fdiv_rn((g.y + g.w) * 0.5f - (a.y + a.w) * 0.5f, ah);
            r.z = logf(__fdiv_rn(g.z - g.x, aw));
            r.w = logf(__fdiv_rn(g.w - g.y, ah));
            // WEIGHTS = (1,1,1,1) -> identity multiply skipped.
        }
        reinterpret_cast<float4*>(out + N)[i] = r;  // out+N 16B-aligned (N%4==0)
        out[5 * N + i] = pos ? 1.0f : 0.0f;
    }

    // ---------------- flush per-gt partials, elect last block ----------------
    __syncthreads();
    if (tid < M) {
        const unsigned long long v = sp[tid];
        if (v) atomicMax(&g_packed[tid], v);
    }
    __threadfence();
    __syncthreads();
    if (tid == 0)
        s_last = (atomicAdd(&g_ticket, 1u) == (unsigned)(gridDim.x - 1));
    __syncthreads();

    // ---------------- last block: patch forced positives ----------------
    if (s_last) {
        __threadfence();             // acquire: see all blocks' writes
        if (tid == 0) g_ticket = 0;  // reset for next graph replay
        if (tid < M) {
            const unsigned long long v = g_packed[tid];
            g_packed[tid] = 0ULL;    // consume-and-reset for next replay

            // v==0 <=> all-zero IoU column: reference argmax picks anchor 0.
            const unsigned ai = v ? (0xFFFFFFFFu - (unsigned)(v & 0xFFFFFFFFull)) : 0u;
            if (ai < (unsigned)N) {
                const int j = g_midx[ai];
                out[ai] = (float)slab[j];

                const float eps = 1.1920929e-7f;
                const float4 av = anchors[ai];
                const float4 g  = sg[j];     // gt tile still live in this block
                const float aw = fmaxf(av.z - av.x, eps);
                const float ah = fmaxf(av.w - av.y, eps);
                float4 r;
                r.x = __fdiv_rn((g.x + g.z) * 0.5f - (av.x + av.z) * 0.5f, aw);
                r.y = __fdiv_rn((g.y + g.w) * 0.5f - (av.y + av.w) * 0.5f, ah);
                r.z = logf(__fdiv_rn(g.z - g.x, aw));
                r.w = logf(__fdiv_rn(g.w - g.y, ah));
                reinterpret_cast<float4*>(out + N)[ai] = r;

                out[5 * N + ai] = 1.0f;
            }
        }
    }
}

// ---------------------------------------------------------------------------
extern "C" void kernel_launch(void* const* d_in, const int* in_sizes, int n_in,
                              void* d_out, int out_size)
{
    const float4* anchors = (const float4*)d_in[0];
    const float4* gts     = (const float4*)d_in[1];
    const int*    labels  = (const int*)d_in[2];
    float*        out     = (float*)d_out;

    const int N = in_sizes[0] / 4;
    const int M = in_sizes[1] / 4;   // 128

    const int blocks = (N + TPB - 1) / TPB;

    k_iou<<<blocks, TPB>>>(anchors, gts, labels, out, N, M);
}